// round 15
// baseline (speedup 1.0000x reference)
#include <cuda_runtime.h>
#include <cstdint>

typedef unsigned long long ull;

#define BATCH 1024
#define TLEN  200
#define DDIM  128
#define HDIM  128
#define NXC   384
#define MROWS (BATCH * TLEN)
#define GROUPS 256

// compact x-projection (sorted-row-major) + perm/offsets
__device__ float g_xproj[(size_t)MROWS * NXC];
__device__ int   g_perm[BATCH];
__device__ int   g_coff[BATCH + 1];
// packed tf32 hi/lo W fragments (B operand): [3 ct][16 nf][16 ks][32 lane] uint4
__device__ uint4 g_wpack[3 * 16 * 16 * 32];

// ---------- packed f32x2 helpers ----------
__device__ __forceinline__ ull pack2(float x, float y) {
    ull r; asm("mov.b64 %0,{%1,%2};" : "=l"(r) : "f"(x), "f"(y)); return r;
}
__device__ __forceinline__ float2 unpack2(ull v) {
    float2 f; asm("mov.b64 {%0,%1},%2;" : "=f"(f.x), "=f"(f.y) : "l"(v)); return f;
}
__device__ __forceinline__ void ffma2(ull &d, ull a, ull b) {
    asm("fma.rn.f32x2 %0,%1,%2,%0;" : "+l"(d) : "l"(a), "l"(b));
}
__device__ __forceinline__ ull addf2(ull a, ull b) {
    ull r; asm("add.rn.f32x2 %0,%1,%2;" : "=l"(r) : "l"(a), "l"(b)); return r;
}
__device__ __forceinline__ float tanhap(float x) {
    float r; asm("tanh.approx.f32 %0,%1;" : "=f"(r) : "f"(x)); return r;
}
__device__ __forceinline__ float sigap(float x) {
    return fmaf(tanhap(0.5f * x), 0.5f, 0.5f);
}
__device__ __forceinline__ uint32_t tf32rna(float x) {
    uint32_t r; asm("cvt.rna.tf32.f32 %0, %1;" : "=r"(r) : "f"(x)); return r;
}
// mma.sync m16n8k8 tf32: D += A*B (acc in-place)
__device__ __forceinline__ void mma8(float* d, uint32_t a0, uint32_t a1, uint32_t a2, uint32_t a3,
                                     uint32_t b0, uint32_t b1) {
    asm volatile("mma.sync.aligned.m16n8k8.row.col.f32.tf32.tf32.f32 "
        "{%0,%1,%2,%3}, {%4,%5,%6,%7}, {%8,%9}, {%0,%1,%2,%3};"
        : "+f"(d[0]), "+f"(d[1]), "+f"(d[2]), "+f"(d[3])
        : "r"(a0), "r"(a1), "r"(a2), "r"(a3), "r"(b0), "r"(b1));
}

// =====================================================================
// Kernel 0: counting sort rows by seq_len DESC -> g_perm; exclusive
// prefix sum of sorted lengths -> g_coff.
// =====================================================================
__global__ void __launch_bounds__(1024) dien_sort_kernel(const int* __restrict__ seq)
{
    __shared__ int s[1024];
    __shared__ int sperm[1024];
    __shared__ int cnt[256];
    __shared__ int cur[256];
    __shared__ int buf[1024];
    const int tid = threadIdx.x;

    s[tid] = seq[tid];
    if (tid < 256) { cnt[tid] = 0; cur[tid] = 0; }
    __syncthreads();
    atomicAdd(&cnt[s[tid] & 255], 1);
    __syncthreads();
    if (tid < 256) buf[tid] = cnt[tid];
    __syncthreads();
    for (int off = 1; off < 256; off <<= 1) {
        int v = 0;
        if (tid < 256) { v = buf[tid]; if (tid + off < 256) v += buf[tid + off]; }
        __syncthreads();
        if (tid < 256) buf[tid] = v;
        __syncthreads();
    }
    {
        int v = s[tid] & 255;
        int start = buf[v] - cnt[v];
        int rank = atomicAdd(&cur[v], 1);
        sperm[start + rank] = tid;
    }
    __syncthreads();
    g_perm[tid] = sperm[tid];
    int sl = s[sperm[tid]];
    buf[tid] = sl;
    __syncthreads();
    for (int off = 1; off < 1024; off <<= 1) {
        int v = buf[tid] + ((tid >= off) ? buf[tid - off] : 0);
        __syncthreads();
        buf[tid] = v;
        __syncthreads();
    }
    g_coff[tid] = buf[tid] - sl;
    if (tid == 1023) g_coff[1024] = buf[1023];
}

// =====================================================================
// Kernel 0b: pack W as B-operand fragments (hi/lo tf32 split).
// =====================================================================
__global__ void __launch_bounds__(256) dien_prep_kernel(
    const float* __restrict__ Wg, const float* __restrict__ Wc)
{
    int idx = blockIdx.x * 256 + threadIdx.x;   // < 3*16*16*32 = 24576
    if (idx >= 24576) return;
    int lane = idx & 31, ks = (idx >> 5) & 15, nf = (idx >> 9) & 15, ct = idx >> 13;
    int tig = lane & 3, gid = lane >> 2;
    int n = ct * 128 + nf * 8 + gid;
    int k0 = ks * 8 + tig, k1 = k0 + 4;

    float w0 = (n < 256) ? Wg[k0 * 256 + n] : Wc[k0 * 128 + n - 256];
    float w1 = (n < 256) ? Wg[k1 * 256 + n] : Wc[k1 * 128 + n - 256];

    uint4 rec;
    rec.x = tf32rna(w0);
    rec.y = tf32rna(w1);
    rec.z = tf32rna(w0 - __uint_as_float(rec.x));
    rec.w = tf32rna(w1 - __uint_as_float(rec.y));
    g_wpack[idx] = rec;
}

// =====================================================================
// Phase 1 (unchanged R14): split-tf32 mma.sync xproj, 32-row warp tiles.
// =====================================================================
__global__ void __launch_bounds__(256, 1) dien_xproj_mma(
    const float* __restrict__ X,
    const float* __restrict__ bg, const float* __restrict__ bc)
{
    extern __shared__ char smraw[];
    float* Xs    = (float*)smraw;                    // [16 rt][16 ks][32 lane][4] fp32 = 131072 B
    float* stage = (float*)(smraw + 131072);         // [128 row][132]                 = 67584 B
    float* sbias = (float*)(smraw + 131072 + 67584); // 384
    int* scoff   = (int*)((char*)sbias + 1536);      // 1025
    int* srcrow  = scoff + 1025;                     // 256

    const int tid  = threadIdx.x;
    const int lane = tid & 31;
    const int w    = tid >> 5;
    const int r0   = blockIdx.x * 256;

    const int total = g_coff[1024];
    if (r0 >= total) return;

    for (int i = tid; i < 1025; i += 256) scoff[i] = g_coff[i];
    for (int i = tid; i < 384; i += 256) sbias[i] = (i < 256) ? bg[i] : bc[i - 256];
    __syncthreads();
    {
        int vr = r0 + tid;
        int sr = -1;
        if (vr < total) {
            int lo = 0, hi = 1024;
            while (hi - lo > 1) { int mid = (lo + hi) >> 1; if (scoff[mid] <= vr) lo = mid; else hi = mid; }
            sr = g_perm[lo] * TLEN + (vr - scoff[lo]);
        }
        srcrow[tid] = sr;
    }
    __syncthreads();

    {
        const float4* X4 = (const float4*)X;
        for (int idx = tid; idx < 8192; idx += 256) {
            int row = idx >> 5, k4 = idx & 31;
            int sr = srcrow[row];
            float4 v = make_float4(0.f, 0.f, 0.f, 0.f);
            if (sr >= 0) v = X4[(size_t)sr * 32 + k4];
            int rt = row >> 4, r16 = row & 15;
            int gid = r16 & 7, half = r16 >> 3;
            #pragma unroll
            for (int j = 0; j < 4; j++) {
                int k = k4 * 4 + j;
                float x = (j == 0) ? v.x : (j == 1) ? v.y : (j == 2) ? v.z : v.w;
                int ks = k >> 3, kk = k & 7;
                int tg = kk & 3, kh = kk >> 2;
                Xs[((rt * 16 + ks) * 32 + gid * 4 + tg) * 4 + half + 2 * kh] = x;
            }
        }
    }
    __syncthreads();

    const float4* Xs4 = (const float4*)Xs;

    for (int round = 0; round < 3; round++) {
        float acc[2][16][4];
        #pragma unroll
        for (int mt = 0; mt < 2; mt++)
            #pragma unroll
            for (int nf = 0; nf < 16; nf++)
                #pragma unroll
                for (int i = 0; i < 4; i++) acc[mt][nf][i] = 0.f;

        const uint4* wp = g_wpack + ((size_t)round * 16 * 16) * 32 + lane;

        #pragma unroll 2
        for (int ks = 0; ks < 16; ks++) {
            uint32_t AH[2][4], AL[2][4];
            #pragma unroll
            for (int mt = 0; mt < 2; mt++) {
                float4 a = Xs4[((w * 2 + mt) * 16 + ks) * 32 + lane];
                float av[4] = {a.x, a.y, a.z, a.w};
                #pragma unroll
                for (int i = 0; i < 4; i++) {
                    uint32_t h = tf32rna(av[i]);
                    AH[mt][i] = h;
                    AL[mt][i] = tf32rna(av[i] - __uint_as_float(h));
                }
            }
            #pragma unroll
            for (int nf = 0; nf < 16; nf++) {
                uint4 b = __ldg(wp + ((size_t)nf * 16 + ks) * 32);
                mma8(acc[0][nf], AH[0][0], AH[0][1], AH[0][2], AH[0][3], b.x, b.y);
                mma8(acc[0][nf], AH[0][0], AH[0][1], AH[0][2], AH[0][3], b.z, b.w);
                mma8(acc[0][nf], AL[0][0], AL[0][1], AL[0][2], AL[0][3], b.x, b.y);
                mma8(acc[1][nf], AH[1][0], AH[1][1], AH[1][2], AH[1][3], b.x, b.y);
                mma8(acc[1][nf], AH[1][0], AH[1][1], AH[1][2], AH[1][3], b.z, b.w);
                mma8(acc[1][nf], AL[1][0], AL[1][1], AL[1][2], AL[1][3], b.x, b.y);
            }
        }

        #pragma unroll
        for (int h = 0; h < 2; h++) {
            if ((w >> 2) == h) {
                int wl = w & 3;
                #pragma unroll
                for (int mt = 0; mt < 2; mt++) {
                    int row0 = wl * 32 + mt * 16 + (lane >> 2);
                    int row1 = row0 + 8;
                    int cb = (lane & 3) * 2;
                    #pragma unroll
                    for (int nf = 0; nf < 16; nf++) {
                        int c0 = nf * 8 + cb, c1 = c0 + 1;
                        float b0 = sbias[round * 128 + c0];
                        float b1 = sbias[round * 128 + c1];
                        stage[row0 * 132 + c0] = acc[mt][nf][0] + b0;
                        stage[row0 * 132 + c1] = acc[mt][nf][1] + b1;
                        stage[row1 * 132 + c0] = acc[mt][nf][2] + b0;
                        stage[row1 * 132 + c1] = acc[mt][nf][3] + b1;
                    }
                }
            }
            __syncthreads();
            for (int idx = tid; idx < 128 * 32; idx += 256) {
                int row = idx >> 5, c4 = idx & 31;
                int vr = r0 + h * 128 + row;
                if (vr < total) {
                    const float* sp = stage + row * 132 + c4 * 4;
                    *(float4*)&g_xproj[(size_t)vr * NXC + round * 128 + c4 * 4] =
                        make_float4(sp[0], sp[1], sp[2], sp[3]);
                }
            }
            __syncthreads();
        }
    }
}

// =====================================================================
// Phase 2: k-parity GRU. 256 CTAs x 512 thr, sorted 4-row groups.
// f32x2 lanes = (k, k+1). h / r*h stored SCALAR [row][128].
// Gate weights pre-packed ull in regs; cand weights pre-packed ull smem.
// ZERO dup movs. Epilogues use all 512 threads (thread = (jc, row=q)).
// =====================================================================
__global__ void __launch_bounds__(512, 1) dien_gru_kernel(
    const float* __restrict__ Wg, const float* __restrict__ Wc,
    const int* __restrict__ seqlen, float* __restrict__ out)
{
    extern __shared__ char smraw[];
    ull*   whcP = (ull*)smraw;                  // [64 k2][128 jc] (w2k,w2k+1)  65536 B
    float* hp   = (float*)(smraw + 65536);      // [4 row][128] scalar           2048 B
    float* rhp  = hp + 512;                     // [4 row][128] scalar           2048 B
    ull*   red  = (ull*)(smraw + 65536 + 4096); // 4096 ull                     32768 B

    const int tid = threadIdx.x;
    const int jc  = tid & 127;
    const int q   = tid >> 7;            // 0..3: k-split for GEMVs, ROW for epilogues
    const int k0  = q * 32;

    // ---- cand weights pre-packed (w[2k2], w[2k2+1]) ----
    for (int i = tid; i < 64 * 128; i += 512) {
        int k2 = i >> 7, jcc = i & 127;
        whcP[i] = pack2(Wc[(size_t)(128 + 2 * k2) * 128 + jcc],
                        Wc[(size_t)(128 + 2 * k2 + 1) * 128 + jcc]);
    }
    // ---- gate weights: 16+16 pre-packed ull in regs ----
    ull wgr2[16], wgu2[16];
    #pragma unroll
    for (int i = 0; i < 16; i++) {
        wgr2[i] = pack2(Wg[(size_t)(128 + k0 + 2 * i) * 256 + jc],
                        Wg[(size_t)(128 + k0 + 2 * i + 1) * 256 + jc]);
        wgu2[i] = pack2(Wg[(size_t)(128 + k0 + 2 * i) * 256 + jc + 128],
                        Wg[(size_t)(128 + k0 + 2 * i + 1) * 256 + jc + 128]);
    }

    const int g = blockIdx.x;
    const int myrow = g_perm[4 * g + q];           // this thread's epilogue row
    const int sq    = seqlen[myrow];
    const int cof   = g_coff[4 * g + q];
    const int maxseq = seqlen[g_perm[4 * g]];      // sorted desc

    hp[tid] = 0.f;
    __syncthreads();

    const float* xrow = g_xproj + (size_t)cof * NXC + jc;
    float* orow = out + (size_t)myrow * TLEN * HDIM + jc;

    for (int t = 0; t < maxseq; t++) {
        // prefetch x-projections for this thread's row
        float xr = 0.f, xu = 0.f, xc = 0.f;
        if (t < sq) {
            const float* p = xrow + (size_t)t * NXC;
            xr = p[0]; xu = p[128]; xc = p[256];
        }

        // ---- gate GEMV partials: 2 gates x 4 rows, k in [k0,k0+32) ----
        ull accR[4] = {0,0,0,0}, accU[4] = {0,0,0,0};
        #pragma unroll
        for (int i = 0; i < 8; i++) {
            ull w0 = wgr2[2 * i], w1 = wgr2[2 * i + 1];
            ull v0 = wgu2[2 * i], v1 = wgu2[2 * i + 1];
            #pragma unroll
            for (int r = 0; r < 4; r++) {
                ulonglong2 hv = ((const ulonglong2*)(hp + r * 128 + k0))[i];  // broadcast
                ffma2(accR[r], hv.x, w0); ffma2(accR[r], hv.y, w1);
                ffma2(accU[r], hv.x, v0); ffma2(accU[r], hv.y, v1);
            }
        }
        // stage: red[q*1024 + {r:0,u:512} + row*128 + jc]
        {
            ull* st = red + q * 1024 + jc;
            #pragma unroll
            for (int r = 0; r < 4; r++) { st[r * 128] = accR[r]; st[512 + r * 128] = accU[r]; }
        }
        __syncthreads();

        // ---- gate epilogue: thread (jc, row=q) ----
        float r_g, u_g, Ho;
        {
            const ull* rd = red + q * 128 + jc;
            ull zr = rd[0], zu = rd[512];
            #pragma unroll
            for (int qq = 1; qq < 4; qq++) {
                zr = addf2(zr, rd[qq * 1024]);
                zu = addf2(zu, rd[qq * 1024 + 512]);
            }
            float2 Zr = unpack2(zr), Zu = unpack2(zu);
            r_g = sigap(Zr.x + Zr.y + xr);
            u_g = sigap(Zu.x + Zu.y + xu);
            Ho = hp[q * 128 + jc];
            rhp[q * 128 + jc] = r_g * Ho;
        }
        __syncthreads();

        // ---- cand GEMV partials: 4 rows, k in [k0,k0+32), packed weights ----
        ull accC[4] = {0,0,0,0};
        {
            const ull* wcb = whcP + (k0 >> 1) * 128 + jc;
            #pragma unroll
            for (int i = 0; i < 8; i++) {
                ull w0 = wcb[(2 * i) * 128];
                ull w1 = wcb[(2 * i + 1) * 128];
                #pragma unroll
                for (int r = 0; r < 4; r++) {
                    ulonglong2 rv = ((const ulonglong2*)(rhp + r * 128 + k0))[i];  // broadcast
                    ffma2(accC[r], rv.x, w0); ffma2(accC[r], rv.y, w1);
                }
            }
        }
        // stage: red[q*512 + row*128 + jc]
        {
            ull* st = red + q * 512 + jc;
            #pragma unroll
            for (int r = 0; r < 4; r++) st[r * 128] = accC[r];
        }
        __syncthreads();

        // ---- cand epilogue + state update: thread (jc, row=q) ----
        {
            const ull* rd = red + q * 128 + jc;
            ull zc = rd[0];
            #pragma unroll
            for (int qq = 1; qq < 4; qq++) zc = addf2(zc, rd[qq * 512]);
            float2 Zc = unpack2(zc);
            float c = tanhap(Zc.x + Zc.y + xc);
            float hn = fmaf(u_g, Ho - c, c);       // u*h + (1-u)*c
            bool v = t < sq;
            hp[q * 128 + jc] = v ? hn : Ho;
            if (v) orow[(size_t)t * HDIM] = hn;
        }
        __syncthreads();
    }

    // ---- tail zero-fill: out[row, t>=seq, :] = 0 ----
    {
        for (int i = sq * HDIM + (tid & 127) + (q * 128 % HDIM); 0; ) break;
    }
    #pragma unroll
    for (int rr = 0; rr < 4; rr++) {
        int row = g_perm[4 * g + rr];
        int s = seqlen[row];
        float* op = out + (size_t)row * TLEN * HDIM;
        for (int i = s * HDIM + tid; i < TLEN * HDIM; i += 512) op[i] = 0.f;
    }
}

// =====================================================================
extern "C" void kernel_launch(void* const* d_in, const int* in_sizes, int n_in,
                              void* d_out, int out_size)
{
    const float* X   = (const float*)d_in[0];
    const int*   seq = (const int*)  d_in[1];
    const float* Wg  = (const float*)d_in[2];
    const float* bg  = (const float*)d_in[3];
    const float* Wc  = (const float*)d_in[4];
    const float* bc  = (const float*)d_in[5];
    float* out = (float*)d_out;
    (void)in_sizes; (void)n_in; (void)out_size;

    const int SMEM_MMA = 131072 + 67584 + 1536 + 1025 * 4 + 256 * 4 + 256;  // ~205.6 KB
    const int SMEM2 = 65536 + 4096 + 32768;                                 // 102400 B
    cudaFuncSetAttribute(dien_xproj_mma, cudaFuncAttributeMaxDynamicSharedMemorySize, SMEM_MMA);
    cudaFuncSetAttribute(dien_gru_kernel, cudaFuncAttributeMaxDynamicSharedMemorySize, SMEM2);

    dien_sort_kernel<<<1, 1024>>>(seq);
    dien_prep_kernel<<<96, 256>>>(Wg, Wc);
    dien_xproj_mma<<<800, 256, SMEM_MMA>>>(X, bg, bc);
    dien_gru_kernel<<<GROUPS, 512, SMEM2>>>(Wg, Wc, seq, out);
}

// round 16
// speedup vs baseline: 1.2220x; 1.2220x over previous
#include <cuda_runtime.h>
#include <cstdint>

typedef unsigned long long ull;

#define BATCH 1024
#define TLEN  200
#define DDIM  128
#define HDIM  128
#define NXC   384
#define MROWS (BATCH * TLEN)
#define GROUPS 256

// compact x-projection (sorted-row-major) + perm/offsets
__device__ float g_xproj[(size_t)MROWS * NXC];
__device__ int   g_perm[BATCH];
__device__ int   g_coff[BATCH + 1];
// packed tf32 hi/lo W fragments (B operand): [3 ct][16 nf][16 ks][32 lane] uint4
__device__ uint4 g_wpack[3 * 16 * 16 * 32];

// ---------- packed f32x2 helpers ----------
__device__ __forceinline__ ull dup2(float v) {
    ull r; asm("mov.b64 %0,{%1,%1};" : "=l"(r) : "f"(v)); return r;
}
__device__ __forceinline__ ull pack2(float x, float y) {
    ull r; asm("mov.b64 %0,{%1,%2};" : "=l"(r) : "f"(x), "f"(y)); return r;
}
__device__ __forceinline__ float2 unpack2(ull v) {
    float2 f; asm("mov.b64 {%0,%1},%2;" : "=f"(f.x), "=f"(f.y) : "l"(v)); return f;
}
__device__ __forceinline__ void ffma2(ull &d, ull a, ull b) {
    asm("fma.rn.f32x2 %0,%1,%2,%0;" : "+l"(d) : "l"(a), "l"(b));
}
__device__ __forceinline__ ull addf2(ull a, ull b) {
    ull r; asm("add.rn.f32x2 %0,%1,%2;" : "=l"(r) : "l"(a), "l"(b)); return r;
}
__device__ __forceinline__ float tanhap(float x) {
    float r; asm("tanh.approx.f32 %0,%1;" : "=f"(r) : "f"(x)); return r;
}
__device__ __forceinline__ float sigap(float x) {
    return fmaf(tanhap(0.5f * x), 0.5f, 0.5f);
}
__device__ __forceinline__ uint32_t tf32rna(float x) {
    uint32_t r; asm("cvt.rna.tf32.f32 %0, %1;" : "=r"(r) : "f"(x)); return r;
}
// mma.sync m16n8k8 tf32: D += A*B (acc in-place)
__device__ __forceinline__ void mma8(float* d, uint32_t a0, uint32_t a1, uint32_t a2, uint32_t a3,
                                     uint32_t b0, uint32_t b1) {
    asm volatile("mma.sync.aligned.m16n8k8.row.col.f32.tf32.tf32.f32 "
        "{%0,%1,%2,%3}, {%4,%5,%6,%7}, {%8,%9}, {%0,%1,%2,%3};"
        : "+f"(d[0]), "+f"(d[1]), "+f"(d[2]), "+f"(d[3])
        : "r"(a0), "r"(a1), "r"(a2), "r"(a3), "r"(b0), "r"(b1));
}

// =====================================================================
// Kernel 0: counting sort rows by seq_len DESC -> g_perm; exclusive
// prefix sum of sorted lengths -> g_coff.
// =====================================================================
__global__ void __launch_bounds__(1024) dien_sort_kernel(const int* __restrict__ seq)
{
    __shared__ int s[1024];
    __shared__ int sperm[1024];
    __shared__ int cnt[256];
    __shared__ int cur[256];
    __shared__ int buf[1024];
    const int tid = threadIdx.x;

    s[tid] = seq[tid];
    if (tid < 256) { cnt[tid] = 0; cur[tid] = 0; }
    __syncthreads();
    atomicAdd(&cnt[s[tid] & 255], 1);
    __syncthreads();
    if (tid < 256) buf[tid] = cnt[tid];
    __syncthreads();
    for (int off = 1; off < 256; off <<= 1) {
        int v = 0;
        if (tid < 256) { v = buf[tid]; if (tid + off < 256) v += buf[tid + off]; }
        __syncthreads();
        if (tid < 256) buf[tid] = v;
        __syncthreads();
    }
    {
        int v = s[tid] & 255;
        int start = buf[v] - cnt[v];
        int rank = atomicAdd(&cur[v], 1);
        sperm[start + rank] = tid;
    }
    __syncthreads();
    g_perm[tid] = sperm[tid];
    int sl = s[sperm[tid]];
    buf[tid] = sl;
    __syncthreads();
    for (int off = 1; off < 1024; off <<= 1) {
        int v = buf[tid] + ((tid >= off) ? buf[tid - off] : 0);
        __syncthreads();
        buf[tid] = v;
        __syncthreads();
    }
    g_coff[tid] = buf[tid] - sl;
    if (tid == 1023) g_coff[1024] = buf[1023];
}

// =====================================================================
// Kernel 0b: pack W as B-operand fragments (hi/lo tf32 split).
// =====================================================================
__global__ void __launch_bounds__(256) dien_prep_kernel(
    const float* __restrict__ Wg, const float* __restrict__ Wc)
{
    int idx = blockIdx.x * 256 + threadIdx.x;   // < 3*16*16*32 = 24576
    if (idx >= 24576) return;
    int lane = idx & 31, ks = (idx >> 5) & 15, nf = (idx >> 9) & 15, ct = idx >> 13;
    int tig = lane & 3, gid = lane >> 2;
    int n = ct * 128 + nf * 8 + gid;
    int k0 = ks * 8 + tig, k1 = k0 + 4;

    float w0 = (n < 256) ? Wg[k0 * 256 + n] : Wc[k0 * 128 + n - 256];
    float w1 = (n < 256) ? Wg[k1 * 256 + n] : Wc[k1 * 128 + n - 256];

    uint4 rec;
    rec.x = tf32rna(w0);
    rec.y = tf32rna(w1);
    rec.z = tf32rna(w0 - __uint_as_float(rec.x));
    rec.w = tf32rna(w1 - __uint_as_float(rec.y));
    g_wpack[idx] = rec;
}

// =====================================================================
// Phase 1: split-tf32 mma.sync xproj, 32-row warp tiles.
// Epilogue: column-split staging (all warps active), stride-72 stage.
// =====================================================================
__global__ void __launch_bounds__(256, 1) dien_xproj_mma(
    const float* __restrict__ X,
    const float* __restrict__ bg, const float* __restrict__ bc)
{
    extern __shared__ char smraw[];
    float* Xs    = (float*)smraw;                    // [16 rt][16 ks][32 lane][4] fp32 = 131072 B
    float* stage = (float*)(smraw + 131072);         // [256 row][72]                  = 73728 B
    float* sbias = (float*)(smraw + 131072 + 73728); // 384
    int* scoff   = (int*)((char*)sbias + 1536);      // 1025
    int* srcrow  = scoff + 1025;                     // 256

    const int tid  = threadIdx.x;
    const int lane = tid & 31;
    const int w    = tid >> 5;
    const int r0   = blockIdx.x * 256;

    const int total = g_coff[1024];
    if (r0 >= total) return;

    for (int i = tid; i < 1025; i += 256) scoff[i] = g_coff[i];
    for (int i = tid; i < 384; i += 256) sbias[i] = (i < 256) ? bg[i] : bc[i - 256];
    __syncthreads();
    {
        int vr = r0 + tid;
        int sr = -1;
        if (vr < total) {
            int lo = 0, hi = 1024;
            while (hi - lo > 1) { int mid = (lo + hi) >> 1; if (scoff[mid] <= vr) lo = mid; else hi = mid; }
            sr = g_perm[lo] * TLEN + (vr - scoff[lo]);
        }
        srcrow[tid] = sr;
    }
    __syncthreads();

    // ---- gather X rows (fp32) into A-fragment layout ----
    {
        const float4* X4 = (const float4*)X;
        for (int idx = tid; idx < 8192; idx += 256) {
            int row = idx >> 5, k4 = idx & 31;
            int sr = srcrow[row];
            float4 v = make_float4(0.f, 0.f, 0.f, 0.f);
            if (sr >= 0) v = X4[(size_t)sr * 32 + k4];
            int rt = row >> 4, r16 = row & 15;
            int gid = r16 & 7, half = r16 >> 3;
            #pragma unroll
            for (int j = 0; j < 4; j++) {
                int k = k4 * 4 + j;
                float x = (j == 0) ? v.x : (j == 1) ? v.y : (j == 2) ? v.z : v.w;
                int ks = k >> 3, kk = k & 7;
                int tg = kk & 3, kh = kk >> 2;
                Xs[((rt * 16 + ks) * 32 + gid * 4 + tg) * 4 + half + 2 * kh] = x;
            }
        }
    }
    __syncthreads();

    const float4* Xs4 = (const float4*)Xs;

    for (int round = 0; round < 3; round++) {
        float acc[2][16][4];
        #pragma unroll
        for (int mt = 0; mt < 2; mt++)
            #pragma unroll
            for (int nf = 0; nf < 16; nf++)
                #pragma unroll
                for (int i = 0; i < 4; i++) acc[mt][nf][i] = 0.f;

        const uint4* wp = g_wpack + ((size_t)round * 16 * 16) * 32 + lane;

        #pragma unroll 2
        for (int ks = 0; ks < 16; ks++) {
            uint32_t AH[2][4], AL[2][4];
            #pragma unroll
            for (int mt = 0; mt < 2; mt++) {
                float4 a = Xs4[((w * 2 + mt) * 16 + ks) * 32 + lane];
                float av[4] = {a.x, a.y, a.z, a.w};
                #pragma unroll
                for (int i = 0; i < 4; i++) {
                    uint32_t h = tf32rna(av[i]);
                    AH[mt][i] = h;
                    AL[mt][i] = tf32rna(av[i] - __uint_as_float(h));
                }
            }
            #pragma unroll
            for (int nf = 0; nf < 16; nf++) {
                uint4 b = __ldg(wp + ((size_t)nf * 16 + ks) * 32);
                mma8(acc[0][nf], AH[0][0], AH[0][1], AH[0][2], AH[0][3], b.x, b.y);
                mma8(acc[0][nf], AH[0][0], AH[0][1], AH[0][2], AH[0][3], b.z, b.w);
                mma8(acc[0][nf], AL[0][0], AL[0][1], AL[0][2], AL[0][3], b.x, b.y);
                mma8(acc[1][nf], AH[1][0], AH[1][1], AH[1][2], AH[1][3], b.x, b.y);
                mma8(acc[1][nf], AH[1][0], AH[1][1], AH[1][2], AH[1][3], b.z, b.w);
                mma8(acc[1][nf], AL[1][0], AL[1][1], AL[1][2], AL[1][3], b.x, b.y);
            }
        }

        // ---- epilogue: 2 column passes (64 cols each); ALL warps stage ----
        #pragma unroll
        for (int p = 0; p < 2; p++) {
            #pragma unroll
            for (int mt = 0; mt < 2; mt++) {
                int row0 = w * 32 + mt * 16 + (lane >> 2);   // 0..255
                int row1 = row0 + 8;
                int cb = (lane & 3) * 2;
                #pragma unroll
                for (int nfl = 0; nfl < 8; nfl++) {
                    int nf = p * 8 + nfl;
                    int cg = nf * 8 + cb;                    // global col within round-tile
                    int lc = nfl * 8 + cb;                   // local col in stage (0..63)
                    float b0 = sbias[round * 128 + cg];
                    float b1 = sbias[round * 128 + cg + 1];
                    *(float2*)&stage[row0 * 72 + lc] =
                        make_float2(acc[mt][nf][0] + b0, acc[mt][nf][1] + b1);
                    *(float2*)&stage[row1 * 72 + lc] =
                        make_float2(acc[mt][nf][2] + b0, acc[mt][nf][3] + b1);
                }
            }
            __syncthreads();
            // coalesced store: 256 rows x 16 float4-cols
            for (int idx = tid; idx < 4096; idx += 256) {
                int row = idx >> 4, c4 = idx & 15;
                int vr = r0 + row;
                if (vr < total) {
                    const float* sp = stage + row * 72 + c4 * 4;
                    *(float4*)&g_xproj[(size_t)vr * NXC + round * 128 + p * 64 + c4 * 4] =
                        make_float4(sp[0], sp[1], sp[2], sp[3]);
                }
            }
            __syncthreads();
        }
    }
}

// =====================================================================
// Phase 2 (exact R14/R12 kernel): GRU on sorted 4-row groups + tail fill.
// =====================================================================
__global__ void __launch_bounds__(512, 1) dien_gru_kernel(
    const float* __restrict__ Wg, const float* __restrict__ Wc,
    const int* __restrict__ seqlen, float* __restrict__ out)
{
    extern __shared__ char smraw[];
    float* whc = (float*)smraw;                 // [128 k][128 col]   65536 B
    ull*   hp  = (ull*)(smraw + 65536);         // [2 pair][128 k]     2048 B
    ull*   rhp = hp + 256;                      // [2 pair][128 k]     2048 B
    ull*   red = rhp + 256;                     // 4096 ull           32768 B

    const int tid = threadIdx.x;
    const int jc  = tid & 127;
    const int q   = tid >> 7;            // 0..3, k-split 32
    const int k0  = q * 32;

    for (int i = tid; i < 128 * 128; i += 512) whc[i] = Wc[128 * 128 + i];

    float wgr[32], wgu[32];
    #pragma unroll
    for (int i = 0; i < 32; i++) {
        wgr[i] = Wg[(size_t)(128 + k0 + i) * 256 + jc];
        wgu[i] = Wg[(size_t)(128 + k0 + i) * 256 + jc + 128];
    }

    const int g  = blockIdx.x;
    const int rA0 = g_perm[4 * g];
    const int maxseq = seqlen[rA0];

    const int posA = 4 * g + 2 * (q & 1);
    const int posB = posA + 1;
    const int rowA = g_perm[(q < 2) ? posA : 4 * g];
    const int rowB = g_perm[(q < 2) ? posB : 4 * g];
    const int cofA = g_coff[(q < 2) ? posA : 4 * g];
    const int cofB = g_coff[(q < 2) ? posB : 4 * g];
    const int sqa = seqlen[rowA];
    const int sqb = seqlen[rowB];

    if (tid < 256) hp[tid] = 0ull;
    __syncthreads();

    const float* xa = g_xproj + (size_t)cofA * NXC + jc;
    const float* xb = g_xproj + (size_t)cofB * NXC + jc;
    float* oa = out + (size_t)rowA * TLEN * HDIM + jc;
    float* ob = out + (size_t)rowB * TLEN * HDIM + jc;

    const ulonglong2* h2 = (const ulonglong2*)hp  + (k0 >> 1);
    const ulonglong2* r2 = (const ulonglong2*)rhp + (k0 >> 1);
    const float* wcp = whc + k0 * 128 + jc;

    for (int t = 0; t < maxseq; t++) {
        float xra = 0.f, xrb = 0.f, xua = 0.f, xub = 0.f, xca = 0.f, xcb = 0.f;
        if (q < 2) {
            const float* p0 = xa + (size_t)t * NXC;
            const float* p1 = xb + (size_t)t * NXC;
            if (t < sqa) { xra = p0[0]; xua = p0[128]; xca = p0[256]; }
            if (t < sqb) { xrb = p1[0]; xub = p1[128]; xcb = p1[256]; }
        }

        ull ar0 = 0, ar1 = 0, au0 = 0, au1 = 0;
        #pragma unroll
        for (int i = 0; i < 16; i++) {
            ulonglong2 a0 = h2[i];
            ulonglong2 a1 = h2[64 + i];
            ull w0 = dup2(wgr[2 * i]), w1 = dup2(wgr[2 * i + 1]);
            ull v0 = dup2(wgu[2 * i]), v1 = dup2(wgu[2 * i + 1]);
            ffma2(ar0, a0.x, w0); ffma2(ar0, a0.y, w1);
            ffma2(ar1, a1.x, w0); ffma2(ar1, a1.y, w1);
            ffma2(au0, a0.x, v0); ffma2(au0, a0.y, v1);
            ffma2(au1, a1.x, v0); ffma2(au1, a1.y, v1);
        }
        {
            ull* st = red + q * 1024 + jc;
            st[0]   = ar0; st[128] = ar1;
            st[512] = au0; st[640] = au1;
        }
        __syncthreads();

        float r_a, r_b, u_a, u_b; float2 Ho;
        if (q < 2) {
            const ull* rd = red + q * 128 + jc;
            ull zr = rd[0], zu = rd[512];
            #pragma unroll
            for (int qq = 1; qq < 4; qq++) {
                zr = addf2(zr, rd[qq * 1024]);
                zu = addf2(zu, rd[qq * 1024 + 512]);
            }
            float2 Zr = unpack2(zr), Zu = unpack2(zu);
            r_a = sigap(Zr.x + xra); r_b = sigap(Zr.y + xrb);
            u_a = sigap(Zu.x + xua); u_b = sigap(Zu.y + xub);
            Ho = unpack2(hp[q * 128 + jc]);
            rhp[q * 128 + jc] = pack2(r_a * Ho.x, r_b * Ho.y);
        }
        __syncthreads();

        ull c0 = 0, c1 = 0;
        #pragma unroll
        for (int i = 0; i < 16; i++) {
            ulonglong2 a0 = r2[i];
            ulonglong2 a1 = r2[64 + i];
            ull w0 = dup2(wcp[(2 * i) * 128]);
            ull w1 = dup2(wcp[(2 * i + 1) * 128]);
            ffma2(c0, a0.x, w0); ffma2(c0, a0.y, w1);
            ffma2(c1, a1.x, w0); ffma2(c1, a1.y, w1);
        }
        {
            ull* st = red + q * 256 + jc;
            st[0] = c0; st[128] = c1;
        }
        __syncthreads();

        if (q < 2) {
            const ull* rd = red + q * 128 + jc;
            ull zc = rd[0];
            #pragma unroll
            for (int qq = 1; qq < 4; qq++) zc = addf2(zc, rd[qq * 256]);
            float2 Zc = unpack2(zc);
            float c_a = tanhap(Zc.x + xca);
            float c_b = tanhap(Zc.y + xcb);
            float hna = fmaf(u_a, Ho.x - c_a, c_a);
            float hnb = fmaf(u_b, Ho.y - c_b, c_b);
            bool va = t < sqa, vb = t < sqb;
            hp[q * 128 + jc] = pack2(va ? hna : Ho.x, vb ? hnb : Ho.y);
            if (va) oa[(size_t)t * HDIM] = hna;
            if (vb) ob[(size_t)t * HDIM] = hnb;
        }
        __syncthreads();
    }

    // ---- tail zero-fill: out[row, t>=seq, :] = 0 (replaces global memset) ----
    #pragma unroll
    for (int rr = 0; rr < 4; rr++) {
        int row = g_perm[4 * g + rr];
        int s = seqlen[row];
        float* op = out + (size_t)row * TLEN * HDIM;
        for (int i = s * HDIM + tid; i < TLEN * HDIM; i += 512) op[i] = 0.f;
    }
}

// =====================================================================
extern "C" void kernel_launch(void* const* d_in, const int* in_sizes, int n_in,
                              void* d_out, int out_size)
{
    const float* X   = (const float*)d_in[0];
    const int*   seq = (const int*)  d_in[1];
    const float* Wg  = (const float*)d_in[2];
    const float* bg  = (const float*)d_in[3];
    const float* Wc  = (const float*)d_in[4];
    const float* bc  = (const float*)d_in[5];
    float* out = (float*)d_out;
    (void)in_sizes; (void)n_in; (void)out_size;

    const int SMEM_MMA = 131072 + 73728 + 1536 + 1025 * 4 + 256 * 4 + 256;  // ~211.8 KB
    const int SMEM2 = 65536 + 2048 + 2048 + 32768;                          // 102400 B
    cudaFuncSetAttribute(dien_xproj_mma, cudaFuncAttributeMaxDynamicSharedMemorySize, SMEM_MMA);
    cudaFuncSetAttribute(dien_gru_kernel, cudaFuncAttributeMaxDynamicSharedMemorySize, SMEM2);

    dien_sort_kernel<<<1, 1024>>>(seq);
    dien_prep_kernel<<<96, 256>>>(Wg, Wc);
    dien_xproj_mma<<<800, 256, SMEM_MMA>>>(X, bg, bc);
    dien_gru_kernel<<<GROUPS, 512, SMEM2>>>(Wg, Wc, seq, out);
}